// round 12
// baseline (speedup 1.0000x reference)
#include <cuda_runtime.h>
#include <math.h>

#define N_S 1024
#define XD  128
#define HID 256
#define MAIN_CTAS 512

typedef unsigned long long u64;

__device__ __align__(16) float g_xpT[HID * N_S];   // xp transposed: [h][j]
__device__ __align__(16) float g_ypb[N_S * HID];   // yp + b1:       [i][h]
__device__ float g_t0[N_S];
__device__ __align__(16) float g_part[N_S * 4];    // partial exp-sums [i][jq]
__device__ unsigned g_done;                        // ticket (zero-init, self-reset)

// ---------------------------------------------------------------------------
// packed f32x2 helpers (sm_103a)
// ---------------------------------------------------------------------------
__device__ __forceinline__ u64 f2add(u64 a, u64 b) {
    u64 r; asm("add.rn.f32x2 %0,%1,%2;" : "=l"(r) : "l"(a), "l"(b)); return r;
}
__device__ __forceinline__ u64 f2fma(u64 a, u64 b, u64 c) {
    u64 r; asm("fma.rn.f32x2 %0,%1,%2,%3;" : "=l"(r) : "l"(a), "l"(b), "l"(c));
    return r;
}
__device__ __forceinline__ u64 f2relu(u64 a) {
    unsigned lo, hi;
    asm("mov.b64 {%0,%1},%2;" : "=r"(lo), "=r"(hi) : "l"(a));
    float flo = fmaxf(__uint_as_float(lo), 0.f);
    float fhi = fmaxf(__uint_as_float(hi), 0.f);
    u64 r;
    asm("mov.b64 %0,{%1,%2};" : "=l"(r)
        : "r"(__float_as_uint(flo)), "r"(__float_as_uint(fhi)));
    return r;
}
__device__ __forceinline__ u64 dupf(float v) {
    unsigned u = __float_as_uint(v);
    u64 r; asm("mov.b64 %0,{%1,%1};" : "=l"(r) : "r"(u)); return r;
}
__device__ __forceinline__ void unpk(u64 a, float& lo, float& hi) {
    unsigned l, h;
    asm("mov.b64 {%0,%1},%2;" : "=r"(l), "=r"(h) : "l"(a));
    lo = __uint_as_float(l); hi = __uint_as_float(h);
}

// ---------------------------------------------------------------------------
// Projection (unchanged from R8 — ~10.5us measured-by-subtraction).
// ---------------------------------------------------------------------------
#define PJX 34
#define PJ_SMEM_BYTES (2 * 128 * PJX * 8)

__global__ void __launch_bounds__(256) proj_kernel(const float* __restrict__ x,
                                                   const float* __restrict__ y,
                                                   const float* __restrict__ W1,
                                                   const float* __restrict__ b1) {
    extern __shared__ u64 sraw[];
    u64* xd = sraw;               // [128][PJX] x rows as dup pairs
    u64* ws = sraw + 128 * PJX;   // [128][PJX] W true pairs

    const int t    = threadIdx.x;
    const int hb   = blockIdx.x * 32;
    const int rb   = blockIdx.y * 32;
    const int half = blockIdx.z;
    const float* src = (half == 0) ? x : y;
    const float* Wh  = W1 + half * XD * HID;

    #pragma unroll
    for (int c = 0; c < 4; c++) {
        const int lin = t + 256 * c;
        const int r   = lin >> 5;
        const int k4  = lin & 31;
        const float4 v = *reinterpret_cast<const float4*>(
            src + (rb + r) * XD + k4 * 4);
        xd[(k4 * 4 + 0) * PJX + r] = dupf(v.x);
        xd[(k4 * 4 + 1) * PJX + r] = dupf(v.y);
        xd[(k4 * 4 + 2) * PJX + r] = dupf(v.z);
        xd[(k4 * 4 + 3) * PJX + r] = dupf(v.w);
    }
    const ulonglong2* Wp = reinterpret_cast<const ulonglong2*>(Wh);
    #pragma unroll
    for (int c = 0; c < 8; c++) {
        const int lin = t + 256 * c;
        const int k   = lin >> 4;
        const int i2  = lin & 15;
        const ulonglong2 v = Wp[k * 64 + (hb >> 1) + i2];
        *reinterpret_cast<ulonglong2*>(&ws[k * PJX + i2 * 2]) = v;
    }
    __syncthreads();

    const int tr = ((t >> 4) & 15) * 2;
    const int th = (t & 15) * 2;

    u64 a00 = 0ull, a01 = 0ull, a10 = 0ull, a11 = 0ull;

    ulonglong2 xr[4], wr[4];
    #pragma unroll
    for (int q = 0; q < 4; q++) {
        xr[q] = *reinterpret_cast<const ulonglong2*>(&xd[q * PJX + tr]);
        wr[q] = *reinterpret_cast<const ulonglong2*>(&ws[q * PJX + th]);
    }

    for (int kb = 0; kb < XD; kb += 4) {
        #pragma unroll
        for (int q = 0; q < 4; q++) {
            const ulonglong2 xv = xr[q];
            const ulonglong2 wv = wr[q];
            if (kb < XD - 4) {
                xr[q] = *reinterpret_cast<const ulonglong2*>(
                    &xd[(kb + 4 + q) * PJX + tr]);
                wr[q] = *reinterpret_cast<const ulonglong2*>(
                    &ws[(kb + 4 + q) * PJX + th]);
            }
            a00 = f2fma(xv.x, wv.x, a00);
            a01 = f2fma(xv.x, wv.y, a01);
            a10 = f2fma(xv.y, wv.x, a10);
            a11 = f2fma(xv.y, wv.y, a11);
        }
    }

    if (half == 0) {
        float lo, hi;
        const int H0 = hb + th, H1 = hb + th + 1;
        const int r0 = rb + tr, r1 = rb + tr + 1;
        unpk(a00, lo, hi);
        g_xpT[(2 * H0) * N_S + r0] = lo; g_xpT[(2 * H0 + 1) * N_S + r0] = hi;
        unpk(a01, lo, hi);
        g_xpT[(2 * H1) * N_S + r0] = lo; g_xpT[(2 * H1 + 1) * N_S + r0] = hi;
        unpk(a10, lo, hi);
        g_xpT[(2 * H0) * N_S + r1] = lo; g_xpT[(2 * H0 + 1) * N_S + r1] = hi;
        unpk(a11, lo, hi);
        g_xpT[(2 * H1) * N_S + r1] = lo; g_xpT[(2 * H1 + 1) * N_S + r1] = hi;
    } else {
        const u64* b1p = reinterpret_cast<const u64*>(b1);
        const int H0 = hb + th, H1 = hb + th + 1;
        const int r0 = rb + tr, r1 = rb + tr + 1;
        const u64 bb0 = b1p[H0], bb1 = b1p[H1];
        *reinterpret_cast<u64*>(&g_ypb[r0 * HID + 2 * H0]) = f2add(a00, bb0);
        *reinterpret_cast<u64*>(&g_ypb[r0 * HID + 2 * H1]) = f2add(a01, bb1);
        *reinterpret_cast<u64*>(&g_ypb[r1 * HID + 2 * H0]) = f2add(a10, bb0);
        *reinterpret_cast<u64*>(&g_ypb[r1 * HID + 2 * H1]) = f2add(a11, bb1);
    }
}

// ---------------------------------------------------------------------------
// Main: T1[i,j] = sum_h relu(ypb[i,h] + xp[j,h]) * W2[h]
// grid 512 = 128 i-blocks (8 rows each, exact) x 4 j-quarters (256 j).
// block 256 = 2 groups x 128 thr; thread = 4 rows x 1 j-pair.
// 4 CTAs/SM (launch_bounds(256,4)). Last CTA finalizes.
// ---------------------------------------------------------------------------
__global__ void __launch_bounds__(256, 4)
main_kernel(const float* __restrict__ W2,
            const float* __restrict__ b2,
            float* __restrict__ out) {
    __shared__ __align__(16) u64 s_y[2][HID][8];   // [g][h][{r0..r3,w,pad}]
    __shared__ float red[32];                      // [row8][4 warps-in-group]
    __shared__ unsigned s_ticket;

    const int t   = threadIdx.x;
    const int ibk = blockIdx.x >> 2;             // i-block 0..127
    const int jq  = blockIdx.x & 3;              // j-quarter
    const int ib  = ibk * 8;

    const int g  = t >> 7;                       // row group 0/1 (rows g*4..g*4+3)
    const int tt = t & 127;
    const int jp = (jq << 7) + tt;               // j-pair index 0..511
    const int j0 = 2 * jp;

    // coalesced staging: word w = sg*2048 + h*8 + si
    #pragma unroll
    for (int it = 0; it < 16; it++) {
        const int w   = t + 256 * it;
        const int sg  = w >> 11;
        const int rem = w & 2047;
        const int h   = rem >> 3;
        const int si  = rem & 7;
        u64 val;
        if (si < 4) {
            val = dupf(g_ypb[(ib + sg * 4 + si) * HID + h]);
        } else {
            val = dupf(W2[h]);                   // slot 4 used; 5-7 pad
        }
        s_y[sg][h][si] = val;
    }
    __syncthreads();

    u64 acc[4];
    #pragma unroll
    for (int i = 0; i < 4; i++) acc[i] = 0ull;

    const u64* xp = reinterpret_cast<const u64*>(g_xpT) + jp;

    u64 xb[8];
    #pragma unroll
    for (int p = 0; p < 8; p++) xb[p] = xp[p * 512];

    for (int hb = 0; hb < HID; hb += 8) {
        #pragma unroll
        for (int p = 0; p < 8; p++) {
            const int h = hb + p;
            const u64 xx = xb[p];
            if (hb < HID - 8) xb[p] = xp[(h + 8) * 512];
            const u64* yrow = s_y[g][h];
            const ulonglong2 ya = *reinterpret_cast<const ulonglong2*>(&yrow[0]);
            const ulonglong2 yb = *reinterpret_cast<const ulonglong2*>(&yrow[2]);
            const u64 ww = yrow[4];
            acc[0] = f2fma(f2relu(f2add(ya.x, xx)), ww, acc[0]);
            acc[1] = f2fma(f2relu(f2add(ya.y, xx)), ww, acc[1]);
            acc[2] = f2fma(f2relu(f2add(yb.x, xx)), ww, acc[2]);
            acc[3] = f2fma(f2relu(f2add(yb.y, xx)), ww, acc[3]);
        }
    }

    const float b2v = b2[0];
    const int lane = t & 31;
    const int wrp  = (t >> 5) & 3;               // warp within group

    #pragma unroll
    for (int i = 0; i < 4; i++) {
        const int rloc = g * 4 + i;              // 0..7
        const int ig   = ib + rloc;
        float v0, v1;
        unpk(acc[i], v0, v1);
        v0 += b2v; v1 += b2v;
        if (j0     == ig) g_t0[ig] = v0;         // diagonal T0
        if (j0 + 1 == ig) g_t0[ig] = v1;
        float s = __expf(v0) + __expf(v1);
        #pragma unroll
        for (int o = 16; o > 0; o >>= 1) s += __shfl_xor_sync(0xffffffffu, s, o);
        if (lane == 0) red[rloc * 4 + wrp] = s;
    }
    __syncthreads();

    if (t < 32) {
        const int row = t >> 2;                  // 0..7
        float v = red[t];
        v += __shfl_xor_sync(0xffffffffu, v, 1);
        v += __shfl_xor_sync(0xffffffffu, v, 2);
        if ((t & 3) == 0) g_part[(ib + row) * 4 + jq] = v;
    }

    // ---- last-CTA finalize ----
    __threadfence();
    __syncthreads();
    if (t == 0) s_ticket = atomicAdd(&g_done, 1u);
    __syncthreads();
    if (s_ticket == MAIN_CTAS - 1) {
        float* fb = reinterpret_cast<float*>(&s_y[0][0][0]);
        float a = 0.f, b = 0.f;
        #pragma unroll
        for (int p = 0; p < 4; p++) {
            const int i = t + 256 * p;
            const float4 q = *reinterpret_cast<const float4*>(&g_part[4 * i]);
            a += g_t0[i];
            b += logf(q.x + q.y + q.z + q.w);
        }
        fb[t] = a; fb[256 + t] = b;
        __syncthreads();
        for (int off = 128; off > 0; off >>= 1) {
            if (t < off) {
                fb[t]       += fb[t + off];
                fb[256 + t] += fb[256 + t + off];
            }
            __syncthreads();
        }
        if (t == 0) {
            out[0] = fb[0] / (float)N_S
                   - (fb[256] / (float)N_S - logf((float)N_S));
            g_done = 0;                          // reset for next replay
        }
    }
}

// ---------------------------------------------------------------------------
extern "C" void kernel_launch(void* const* d_in, const int* in_sizes, int n_in,
                              void* d_out, int out_size) {
    const float* x  = (const float*)d_in[0];
    const float* y  = (const float*)d_in[1];
    const float* W1 = (const float*)d_in[2];
    const float* b1 = (const float*)d_in[3];
    const float* W2 = (const float*)d_in[4];
    const float* b2 = (const float*)d_in[5];

    cudaFuncSetAttribute(proj_kernel,
                         cudaFuncAttributeMaxDynamicSharedMemorySize,
                         PJ_SMEM_BYTES);

    proj_kernel<<<dim3(4, 32, 2), 256, PJ_SMEM_BYTES>>>(x, y, W1, b1);
    main_kernel<<<MAIN_CTAS, 256>>>(W2, b2, (float*)d_out);
}